// round 8
// baseline (speedup 1.0000x reference)
#include <cuda_runtime.h>
#include <stdint.h>
#include <math.h>

#define B 8
#define S 4194304              // elements per sample (64*256*256)
#define WPS (S / 32)           // visibility words per sample
#define NR 5                   // ranks: med, q25lo, q25hi, q75lo, q75hi
#define NBLK 128               // K1 blocks per sample == compact regions
#define REG 32768              // elements per region (S/NBLK)
#define CAPR 262144            // candidate capacity per target rank
#define CAPM 524288            // candidate capacity for MAD rank

// ---------------- device scratch (static; no allocations) ----------------
static __device__ float    g_cmp[(size_t)B * S];   // compacted visible values
static __device__ unsigned g_visbits[B * WPS];     // 4 MB: bit=1 -> visible
static __device__ int      g_bcnt[B][NBLK];
static __device__ int      g_n[B];
static __device__ int      g_hist0[B][4096];
static __device__ int      g_mhist0[B][2048];
static __device__ unsigned g_cand[B][NR][CAPR];    // 40 MB: target rank candidates (keys)
static __device__ unsigned g_mcand[B][CAPM];       // 16 MB: MAD candidates (raw bits)
static __device__ int      g_ccnt[B * NR];
static __device__ int      g_mccnt[B];
static __device__ unsigned g_prefix[B * NR];       // level-0 bin per rank
static __device__ int      g_rem[B * NR];          // rank index within level-0 bin
static __device__ int      g_rep[B * NR];          // dedup: representative rank with same bin
static __device__ float    g_frac[B][2];
static __device__ float    g_vals[B * NR];
static __device__ float    g_med[B];
static __device__ float    g_q25[B], g_q75[B];
static __device__ unsigned g_mprefix[B];
static __device__ int      g_mrem[B];
static __device__ float    g_madv[B];
static __device__ float    g_scale[B];
static __device__ double   g_lsum;
static __device__ double   g_nmask;

__device__ __forceinline__ unsigned f2key(float x) {
    unsigned u = __float_as_uint(x);
    return (u & 0x80000000u) ? ~u : (u | 0x80000000u);
}
__device__ __forceinline__ float key2f(unsigned k) {
    unsigned u = (k & 0x80000000u) ? (k & 0x7FFFFFFFu) : ~k;
    return __uint_as_float(u);
}

// ---------------- K0: zero scratch ----------------
__global__ void k0_zero() {
    int tid = blockIdx.x * blockDim.x + threadIdx.x;
    int st = gridDim.x * blockDim.x;
    int* p;
    p = (int*)g_hist0;  for (int i = tid; i < B * 4096; i += st) p[i] = 0;
    p = (int*)g_mhist0; for (int i = tid; i < B * 2048; i += st) p[i] = 0;
    if (tid < B * NR) g_ccnt[tid] = 0;
    if (tid < B) g_mccnt[tid] = 0;
    if (tid == 0) g_lsum = 0.0;
}

// ---------------- K1: compact + visbits + 12-bit hist ----------------
// grid (NBLK, B), block 256.
__global__ void __launch_bounds__(256) k1_compact(const float* __restrict__ tgt,
                                                   const float* __restrict__ msk) {
    __shared__ int sh[4096];
    __shared__ int blkpos;
    const int s = blockIdx.y;
    for (int i = threadIdx.x; i < 4096; i += 256) sh[i] = 0;
    if (threadIdx.x == 0) blkpos = 0;
    __syncthreads();

    const size_t soff = (size_t)s * S;
    const float* t = tgt + soff;
    const float* m = msk + soff;
    float* outv = g_cmp + soff + (size_t)blockIdx.x * REG;
    unsigned* vb = g_visbits + s * WPS;
    const int base = blockIdx.x * REG;
    const int lane = threadIdx.x & 31;

    for (int k = 0; k < 32; k++) {
        const int idx = base + k * 1024 + threadIdx.x * 4;
        const float4 mv = *reinterpret_cast<const float4*>(m + idx);
        const float4 tv = *reinterpret_cast<const float4*>(t + idx);
        const float mm[4] = {mv.x, mv.y, mv.z, mv.w};
        const float tt[4] = {tv.x, tv.y, tv.z, tv.w};
        unsigned vm = 0;
#pragma unroll
        for (int j = 0; j < 4; j++) if (mm[j] < 1.0f) vm |= 1u << j;  // visible <=> clip(m) < 1
#pragma unroll
        for (int j = 0; j < 4; j++)
            if (vm & (1u << j)) atomicAdd(&sh[f2key(tt[j]) >> 20], 1);

        // assemble 32-bit visibility word across 8 consecutive lanes
        unsigned part = vm << (4 * (lane & 7));
        part |= __shfl_xor_sync(0xFFFFFFFFu, part, 1);
        part |= __shfl_xor_sync(0xFFFFFFFFu, part, 2);
        part |= __shfl_xor_sync(0xFFFFFFFFu, part, 4);
        if ((lane & 7) == 0) vb[idx >> 5] = part;

        // warp-aggregated compaction
        int vc = __popc(vm);
        int sc = vc;
#pragma unroll
        for (int d = 1; d < 32; d <<= 1) {
            int v = __shfl_up_sync(0xFFFFFFFFu, sc, d);
            if (lane >= d) sc += v;
        }
        int wtotal = __shfl_sync(0xFFFFFFFFu, sc, 31);
        int wbase = 0;
        if (lane == 0 && wtotal) wbase = atomicAdd(&blkpos, wtotal);
        wbase = __shfl_sync(0xFFFFFFFFu, wbase, 0);
        int o = wbase + sc - vc;
#pragma unroll
        for (int j = 0; j < 4; j++)
            if (vm & (1u << j)) outv[o++] = tt[j];
    }
    __syncthreads();
    if (threadIdx.x == 0) g_bcnt[s][blockIdx.x] = blkpos;
    for (int i = threadIdx.x; i < 4096; i += 256)
        if (sh[i]) atomicAdd(&g_hist0[s][i], sh[i]);
}

// ---------------- block scan helper for k8 ----------------
template <int NB>
__device__ __forceinline__ void scan_find_one(const int* __restrict__ h,
                                              unsigned* pf, int* rem, int shift) {
    constexpr int C = NB / 256;
    const int tid = threadIdx.x, lane = tid & 31, w = tid >> 5;
    __shared__ int wtot[8];
    int c[C]; int tot = 0;
#pragma unroll
    for (int i = 0; i < C; i++) { c[i] = h[tid * C + i]; tot += c[i]; }
    int sc = tot;
#pragma unroll
    for (int d = 1; d < 32; d <<= 1) {
        int v = __shfl_up_sync(0xFFFFFFFFu, sc, d);
        if (lane >= d) sc += v;
    }
    if (lane == 31) wtot[w] = sc;
    const int r = *rem;
    __syncthreads();
    int woff = 0;
#pragma unroll
    for (int i = 0; i < 8; i++) if (i < w) woff += wtot[i];
    int prev = woff + sc - tot;
#pragma unroll
    for (int i = 0; i < C; i++) {
        if (prev <= r && r < prev + c[i]) {
            *pf = ((*pf) << shift) | (unsigned)(tid * C + i);
            *rem = r - prev;
        }
        prev += c[i];
    }
}

// ---------------- K2: ranks + level-0 scan + rep map ----------------
__global__ void k2_setup() {
    const int s = blockIdx.x, tid = threadIdx.x, lane = tid & 31, w = tid >> 5;
    __shared__ int wtot[8];
    int c[16]; int tot = 0;
    const int* h = g_hist0[s];
#pragma unroll
    for (int i = 0; i < 16; i++) { c[i] = h[tid * 16 + i]; tot += c[i]; }
    int sc = tot;
#pragma unroll
    for (int d = 1; d < 32; d <<= 1) {
        int v = __shfl_up_sync(0xFFFFFFFFu, sc, d);
        if (lane >= d) sc += v;
    }
    if (lane == 31) wtot[w] = sc;
    __syncthreads();
    int woff = 0, n = 0;
#pragma unroll
    for (int i = 0; i < 8; i++) { if (i < w) woff += wtot[i]; n += wtot[i]; }
    int prev = woff + sc - tot;

    float nm1 = fmaxf((float)n - 1.0f, 0.0f);
    float p25 = 0.25f * nm1, p75 = 0.75f * nm1;
    float f25 = floorf(p25), f75 = floorf(p75);
    int r[NR];
    r[0] = (n > 0) ? (n - 1) / 2 : 0;
    r[1] = min(max((int)f25, 0), S - 1);
    r[2] = min(max((int)ceilf(p25), 0), S - 1);
    r[3] = min(max((int)f75, 0), S - 1);
    r[4] = min(max((int)ceilf(p75), 0), S - 1);
#pragma unroll
    for (int i = 0; i < 16; i++) {
#pragma unroll
        for (int j = 0; j < NR; j++)
            if (prev <= r[j] && r[j] < prev + c[i]) {
                g_prefix[s * NR + j] = (unsigned)(tid * 16 + i);
                g_rem[s * NR + j]    = r[j] - prev;
            }
        prev += c[i];
    }
    __syncthreads();   // global writes above visible block-wide after sync
    if (tid == 0) {
        g_n[s] = n;
        g_frac[s][0] = p25 - f25;
        g_frac[s][1] = p75 - f75;
        g_mprefix[s] = 0;
        g_mrem[s] = (n > 0) ? (n - 1) / 2 : 0;
        if (n == 0)
            for (int j = 0; j < NR; j++) { g_prefix[s * NR + j] = 0; g_rem[s * NR + j] = 0; }
        // dedup map: rank j gathers only if it is the first with its level-0 bin
        for (int j = 0; j < NR; j++) {
            int rep = j;
            for (int j2 = 0; j2 < j; j2++)
                if (g_prefix[s * NR + j2] == g_prefix[s * NR + j]) { rep = j2; break; }
            g_rep[s * NR + j] = rep;
        }
    }
}

// ---------------- K3g: gather target-rank candidates (one 34MB pass) ----------------
__global__ void __launch_bounds__(256) k3_gather() {
    const int s = blockIdx.y, b = blockIdx.x;
    const int cnt = g_bcnt[s][b];
    const float* v = g_cmp + (size_t)s * S + (size_t)b * REG;
    const float4* v4 = reinterpret_cast<const float4*>(v);
    const int lane = threadIdx.x & 31;
    unsigned pf[NR]; int dorep[NR];
#pragma unroll
    for (int j = 0; j < NR; j++) {
        pf[j] = g_prefix[s * NR + j];
        dorep[j] = (g_rep[s * NR + j] == j);
    }
    const int nvec = cnt >> 2;
    const int iters = (nvec + 255) >> 8;        // uniform across block for ballots
    for (int k = 0; k < iters; k++) {
        const int i = k * 256 + threadIdx.x;
        const bool ok = (i < nvec);
        float4 x = make_float4(0.f, 0.f, 0.f, 0.f);
        if (ok) x = v4[i];
        const float xx[4] = {x.x, x.y, x.z, x.w};
#pragma unroll
        for (int e = 0; e < 4; e++) {
            unsigned key = f2key(xx[e]);
            unsigned top = key >> 20;
#pragma unroll
            for (int j = 0; j < NR; j++) {
                if (!dorep[j]) continue;                     // uniform per block
                bool mt = ok && (top == pf[j]);
                unsigned mask = __ballot_sync(0xFFFFFFFFu, mt);
                if (mask) {
                    int leader = __ffs(mask) - 1;
                    unsigned bse = 0;
                    if (lane == leader) bse = (unsigned)atomicAdd(&g_ccnt[s * NR + j], __popc(mask));
                    bse = __shfl_sync(0xFFFFFFFFu, bse, leader);
                    if (mt) {
                        unsigned off = bse + __popc(mask & ((1u << lane) - 1u));
                        if (off < CAPR) g_cand[s][j][off] = key;
                    }
                }
            }
        }
    }
    // residual (divergent-safe plain atomics)
    for (int i = (nvec << 2) + threadIdx.x; i < cnt; i += 256) {
        unsigned key = f2key(v[i]);
        unsigned top = key >> 20;
#pragma unroll
        for (int j = 0; j < NR; j++) {
            if (dorep[j] && top == pf[j]) {
                unsigned off = (unsigned)atomicAdd(&g_ccnt[s * NR + j], 1);
                if (off < CAPR) g_cand[s][j][off] = key;
            }
        }
    }
}

// ---------------- K4s: per-rank select from candidates ----------------
__global__ void __launch_bounds__(256) k4_select() {
    const int b = blockIdx.x;          // 0..B*NR-1
    const int s = b / NR, j = b % NR;
    __shared__ int sh[4096];
    __shared__ int wtot[8];
    __shared__ int s_bin, s_rem;
    const int tid = threadIdx.x, lane = tid & 31, w = tid >> 5;
    if (g_n[s] <= 0) { if (tid == 0) g_vals[b] = 0.0f; return; }
    const int rep = g_rep[s * NR + j];
    const unsigned* cand = g_cand[s][rep];
    int cnt = g_ccnt[s * NR + rep]; if (cnt > CAPR) cnt = CAPR;
    const int rem0 = g_rem[b];
    for (int i = tid; i < 4096; i += 256) sh[i] = 0;
    __syncthreads();
    for (int i = tid; i < cnt; i += 256) atomicAdd(&sh[(cand[i] >> 8) & 0xFFF], 1);
    __syncthreads();
    // block scan over 4096 bins, find bin containing rem0
    int c[16]; int tot = 0;
#pragma unroll
    for (int i = 0; i < 16; i++) { c[i] = sh[tid * 16 + i]; tot += c[i]; }
    int sc = tot;
#pragma unroll
    for (int d = 1; d < 32; d <<= 1) {
        int v = __shfl_up_sync(0xFFFFFFFFu, sc, d);
        if (lane >= d) sc += v;
    }
    if (lane == 31) wtot[w] = sc;
    __syncthreads();
    int woff = 0;
#pragma unroll
    for (int i = 0; i < 8; i++) if (i < w) woff += wtot[i];
    int prev = woff + sc - tot;
#pragma unroll
    for (int i = 0; i < 16; i++) {
        if (prev <= rem0 && rem0 < prev + c[i]) { s_bin = tid * 16 + i; s_rem = rem0 - prev; }
        prev += c[i];
    }
    __syncthreads();
    const unsigned bin1 = (unsigned)s_bin;
    const int rem1 = s_rem;
    if (tid < 256) sh[tid] = 0;
    __syncthreads();
    for (int i = tid; i < cnt; i += 256) {
        unsigned kk = cand[i];
        if (((kk >> 8) & 0xFFF) == bin1) atomicAdd(&sh[kk & 0xFF], 1);
    }
    __syncthreads();
    if (tid == 0) {
        int r = rem1, cum = 0; unsigned byte = 0;
        for (int x = 0; x < 256; x++) { int cc = sh[x]; if (r < cum + cc) { byte = (unsigned)x; break; } cum += cc; }
        unsigned key = (g_prefix[b] << 20) | (bin1 << 8) | byte;
        g_vals[b] = key2f(key);
    }
}

// ---------------- K6: combine med / q25 / q75 ----------------
__global__ void k6_vals() {
    const int tid = threadIdx.x;  // 1 block, 64 threads
    if (tid < B) {
        const int s = tid;
        g_med[s] = (g_n[s] > 0) ? g_vals[s * NR + 0] : 0.0f;
        g_q25[s] = g_vals[s * NR + 1] + (g_vals[s * NR + 2] - g_vals[s * NR + 1]) * g_frac[s][0];
        g_q75[s] = g_vals[s * NR + 3] + (g_vals[s * NR + 4] - g_vals[s * NR + 3]) * g_frac[s][1];
    }
}

// ---------------- K7: MAD level-0 hist of |t - med| ----------------
__global__ void __launch_bounds__(256) k7_mhist0() {
    __shared__ int sh[2048];
    const int s = blockIdx.y, b = blockIdx.x;
    for (int i = threadIdx.x; i < 2048; i += 256) sh[i] = 0;
    __syncthreads();
    const float med = g_med[s];
    const int cnt = g_bcnt[s][b];
    const float* v = g_cmp + (size_t)s * S + (size_t)b * REG;
    const float4* v4 = reinterpret_cast<const float4*>(v);
    const int nvec = cnt >> 2;
#pragma unroll 4
    for (int i = threadIdx.x; i < nvec; i += 256) {
        const float4 x = v4[i];
        const float xx[4] = {x.x, x.y, x.z, x.w};
#pragma unroll
        for (int e = 0; e < 4; e++)
            atomicAdd(&sh[__float_as_uint(fabsf(xx[e] - med)) >> 20], 1);
    }
    for (int i = (nvec << 2) + threadIdx.x; i < cnt; i += 256)
        atomicAdd(&sh[__float_as_uint(fabsf(v[i] - med)) >> 20], 1);
    __syncthreads();
    for (int i = threadIdx.x; i < 2048; i += 256)
        if (sh[i]) atomicAdd(&g_mhist0[s][i], sh[i]);
}

// ---------------- K8: MAD level-0 scan ----------------
__global__ void k8_mscan0() {
    const int s = blockIdx.x;
    if (g_n[s] <= 0) return;
    scan_find_one<2048>(g_mhist0[s], &g_mprefix[s], &g_mrem[s], 0);
}

// ---------------- K9g: gather MAD candidates ----------------
__global__ void __launch_bounds__(256) k9_gather() {
    const int s = blockIdx.y, b = blockIdx.x;
    const float med = g_med[s];
    const unsigned pf = g_mprefix[s];
    const int cnt = g_bcnt[s][b];
    const float* v = g_cmp + (size_t)s * S + (size_t)b * REG;
    const float4* v4 = reinterpret_cast<const float4*>(v);
    const int lane = threadIdx.x & 31;
    const int nvec = cnt >> 2;
    const int iters = (nvec + 255) >> 8;
    for (int k = 0; k < iters; k++) {
        const int i = k * 256 + threadIdx.x;
        const bool ok = (i < nvec);
        float4 x = make_float4(0.f, 0.f, 0.f, 0.f);
        if (ok) x = v4[i];
        const float xx[4] = {x.x, x.y, x.z, x.w};
#pragma unroll
        for (int e = 0; e < 4; e++) {
            unsigned u = __float_as_uint(fabsf(xx[e] - med));
            bool mt = ok && ((u >> 20) == pf);
            unsigned mask = __ballot_sync(0xFFFFFFFFu, mt);
            if (mask) {
                int leader = __ffs(mask) - 1;
                unsigned bse = 0;
                if (lane == leader) bse = (unsigned)atomicAdd(&g_mccnt[s], __popc(mask));
                bse = __shfl_sync(0xFFFFFFFFu, bse, leader);
                if (mt) {
                    unsigned off = bse + __popc(mask & ((1u << lane) - 1u));
                    if (off < CAPM) g_mcand[s][off] = u;
                }
            }
        }
    }
    for (int i = (nvec << 2) + threadIdx.x; i < cnt; i += 256) {
        unsigned u = __float_as_uint(fabsf(v[i] - med));
        if ((u >> 20) == pf) {
            unsigned off = (unsigned)atomicAdd(&g_mccnt[s], 1);
            if (off < CAPM) g_mcand[s][off] = u;
        }
    }
}

// ---------------- K10s: select MAD from candidates ----------------
__global__ void __launch_bounds__(256) k10_select() {
    const int s = blockIdx.x;
    __shared__ int sh[4096];
    __shared__ int wtot[8];
    __shared__ int s_bin, s_rem;
    const int tid = threadIdx.x, lane = tid & 31, w = tid >> 5;
    if (g_n[s] <= 0) { if (tid == 0) g_madv[s] = 0.0f; return; }
    const unsigned* cand = g_mcand[s];
    int cnt = g_mccnt[s]; if (cnt > CAPM) cnt = CAPM;
    const int rem0 = g_mrem[s];
    for (int i = tid; i < 4096; i += 256) sh[i] = 0;
    __syncthreads();
    for (int i = tid; i < cnt; i += 256) atomicAdd(&sh[(cand[i] >> 8) & 0xFFF], 1);
    __syncthreads();
    int c[16]; int tot = 0;
#pragma unroll
    for (int i = 0; i < 16; i++) { c[i] = sh[tid * 16 + i]; tot += c[i]; }
    int sc = tot;
#pragma unroll
    for (int d = 1; d < 32; d <<= 1) {
        int v = __shfl_up_sync(0xFFFFFFFFu, sc, d);
        if (lane >= d) sc += v;
    }
    if (lane == 31) wtot[w] = sc;
    __syncthreads();
    int woff = 0;
#pragma unroll
    for (int i = 0; i < 8; i++) if (i < w) woff += wtot[i];
    int prev = woff + sc - tot;
#pragma unroll
    for (int i = 0; i < 16; i++) {
        if (prev <= rem0 && rem0 < prev + c[i]) { s_bin = tid * 16 + i; s_rem = rem0 - prev; }
        prev += c[i];
    }
    __syncthreads();
    const unsigned bin1 = (unsigned)s_bin;
    const int rem1 = s_rem;
    if (tid < 256) sh[tid] = 0;
    __syncthreads();
    for (int i = tid; i < cnt; i += 256) {
        unsigned kk = cand[i];
        if (((kk >> 8) & 0xFFF) == bin1) atomicAdd(&sh[kk & 0xFF], 1);
    }
    __syncthreads();
    if (tid == 0) {
        int r = rem1, cum = 0; unsigned byte = 0;
        for (int x = 0; x < 256; x++) { int cc = sh[x]; if (r < cum + cc) { byte = (unsigned)x; break; } cum += cc; }
        g_madv[s] = __uint_as_float((g_mprefix[s] << 20) | (bin1 << 8) | byte);
    }
}

// ---------------- K12: final per-sample scalars + num_masked ----------------
__global__ void k12_final() {
    const int tid = threadIdx.x;  // 32 threads
    if (tid < B) {
        const int s = tid, n = g_n[s];
        float mad = (n > 0) ? g_madv[s] : 0.0f;
        float scaled = 1.4826f * mad;
        float iqr = fmaxf((g_q75[s] - g_q25[s]) / 1.35f, 1e-6f);
        float fm = (scaled < 0.1f) ? iqr : scaled;
        if (n <= 0) fm = 1.0f;
        int dn = (n > 0) && (fm > 0.1f);
        g_scale[s] = dn ? (1.0f / fm) : 1.0f;   // (p-med)/fm - (t-med)/fm == (p-t)/fm
    }
    if (tid == 0) {
        double nm = (double)B * (double)S;      // binary mask: sum(mask) = total - visible
        for (int s2 = 0; s2 < B; s2++) nm -= (double)g_n[s2];
        g_nmask = nm;
    }
}

// ---------------- K13: masked-MSE using visbits (no mask read) ----------------
__global__ void __launch_bounds__(256) k13_loss(const float* __restrict__ pred,
                                                const float* __restrict__ tgt) {
    const int s = blockIdx.y;
    const float sc = g_scale[s];
    const size_t off = (size_t)s * S;
    const float* p = pred + off;
    const float* t = tgt + off;
    const unsigned* vb = g_visbits + s * WPS;
    const int base = blockIdx.x * 8192;
    float ls = 0.0f;
#pragma unroll
    for (int k = 0; k < 8; k++) {
        const int idx = base + k * 1024 + threadIdx.x * 4;
        const float4 pv = *reinterpret_cast<const float4*>(p + idx);
        const float4 tv = *reinterpret_cast<const float4*>(t + idx);
        const unsigned nib = (vb[idx >> 5] >> (idx & 31)) & 0xF;
        const float pp[4] = {pv.x, pv.y, pv.z, pv.w};
        const float tt[4] = {tv.x, tv.y, tv.z, tv.w};
#pragma unroll
        for (int j = 0; j < 4; j++) {
            float d = (pp[j] - tt[j]) * sc;
            float l = fminf(d * d, 100.0f);
            ls += ((nib >> j) & 1u) ? 0.0f : l;   // masked <=> not visible
        }
    }
    for (int o = 16; o; o >>= 1) ls += __shfl_down_sync(0xFFFFFFFFu, ls, o);
    __shared__ float wls[8];
    if ((threadIdx.x & 31) == 0) wls[threadIdx.x >> 5] = ls;
    __syncthreads();
    if (threadIdx.x == 0) {
        double a = 0.0;
        for (int i = 0; i < 8; i++) a += (double)wls[i];
        atomicAdd(&g_lsum, a);
    }
}

// ---------------- K14: write scalar output ----------------
__global__ void k14_out(float* out) {
    double nm = g_nmask;
    out[0] = (nm > 0.0) ? (float)(g_lsum / fmax(nm, 1.0)) : 0.0f;
}

// ---------------- launch ----------------
extern "C" void kernel_launch(void* const* d_in, const int* in_sizes, int n_in,
                              void* d_out, int out_size) {
    const float* pred = (const float*)d_in[0];
    const float* tgt  = (const float*)d_in[1];
    const float* msk  = (const float*)d_in[2];
    float* out = (float*)d_out;

    dim3 greg(NBLK, B), gloss(512, B);

    k0_zero<<<64, 256>>>();
    k1_compact<<<greg, 256>>>(tgt, msk);
    k2_setup<<<B, 256>>>();
    k3_gather<<<greg, 256>>>();
    k4_select<<<B * NR, 256>>>();
    k6_vals<<<1, 64>>>();
    k7_mhist0<<<greg, 256>>>();
    k8_mscan0<<<B, 256>>>();
    k9_gather<<<greg, 256>>>();
    k10_select<<<B, 256>>>();
    k12_final<<<1, 32>>>();
    k13_loss<<<gloss, 256>>>(pred, tgt);
    k14_out<<<1, 1>>>(out);
}

// round 9
// speedup vs baseline: 2.3871x; 2.3871x over previous
#include <cuda_runtime.h>
#include <stdint.h>
#include <math.h>

#define B 8
#define S 4194304              // elements per sample (64*256*256)
#define WPS (S / 32)           // visibility words per sample
#define NR 5                   // ranks: med, q25lo, q25hi, q75lo, q75hi
#define NBLK 128               // K1 blocks per sample == compact regions
#define REG 32768              // elements per region (S/NBLK)
#define CAPR 262144            // candidate capacity per target rank
#define CAPM 524288            // candidate capacity for MAD rank
#define SBUF 1536              // per-block staging per rank
#define SBUFM 4096             // per-block staging for MAD

// ---------------- device scratch (static; no allocations) ----------------
static __device__ float    g_cmp[(size_t)B * S];   // compacted visible values
static __device__ unsigned g_visbits[B * WPS];     // 4 MB: bit=1 -> visible
static __device__ int      g_bcnt[B][NBLK];
static __device__ int      g_n[B];
static __device__ int      g_hist0[B][4096];
static __device__ int      g_mhist0[B][2048];
static __device__ unsigned g_cand[B][NR][CAPR];    // target rank candidates (keys)
static __device__ unsigned g_mcand[B][CAPM];       // MAD candidates (raw bits)
static __device__ int      g_ccnt[B * NR];
static __device__ int      g_mccnt[B];
static __device__ unsigned g_prefix[B * NR];       // level-0 bin per rank
static __device__ int      g_rem[B * NR];          // rank index within level-0 bin
static __device__ int      g_rep[B * NR];          // dedup: representative rank with same bin
static __device__ float    g_frac[B][2];
static __device__ float    g_vals[B * NR];
static __device__ float    g_med[B];
static __device__ float    g_q25[B], g_q75[B];
static __device__ unsigned g_mprefix[B];
static __device__ int      g_mrem[B];
static __device__ float    g_madv[B];
static __device__ float    g_scale[B];
static __device__ double   g_lsum;
static __device__ double   g_nmask;

__device__ __forceinline__ unsigned f2key(float x) {
    unsigned u = __float_as_uint(x);
    return (u & 0x80000000u) ? ~u : (u | 0x80000000u);
}
__device__ __forceinline__ float key2f(unsigned k) {
    unsigned u = (k & 0x80000000u) ? (k & 0x7FFFFFFFu) : ~k;
    return __uint_as_float(u);
}

// ---------------- K0: zero scratch ----------------
__global__ void k0_zero() {
    int tid = blockIdx.x * blockDim.x + threadIdx.x;
    int st = gridDim.x * blockDim.x;
    int* p;
    p = (int*)g_hist0;  for (int i = tid; i < B * 4096; i += st) p[i] = 0;
    p = (int*)g_mhist0; for (int i = tid; i < B * 2048; i += st) p[i] = 0;
    if (tid < B * NR) g_ccnt[tid] = 0;
    if (tid < B) g_mccnt[tid] = 0;
    if (tid == 0) g_lsum = 0.0;
}

// ---------------- K1: compact + visbits + 12-bit hist ----------------
// grid (NBLK, B), block 256.
__global__ void __launch_bounds__(256) k1_compact(const float* __restrict__ tgt,
                                                   const float* __restrict__ msk) {
    __shared__ int sh[4096];
    __shared__ int blkpos;
    const int s = blockIdx.y;
    for (int i = threadIdx.x; i < 4096; i += 256) sh[i] = 0;
    if (threadIdx.x == 0) blkpos = 0;
    __syncthreads();

    const size_t soff = (size_t)s * S;
    const float* t = tgt + soff;
    const float* m = msk + soff;
    float* outv = g_cmp + soff + (size_t)blockIdx.x * REG;
    unsigned* vb = g_visbits + s * WPS;
    const int base = blockIdx.x * REG;
    const int lane = threadIdx.x & 31;

    for (int k = 0; k < 32; k++) {
        const int idx = base + k * 1024 + threadIdx.x * 4;
        const float4 mv = *reinterpret_cast<const float4*>(m + idx);
        const float4 tv = *reinterpret_cast<const float4*>(t + idx);
        const float mm[4] = {mv.x, mv.y, mv.z, mv.w};
        const float tt[4] = {tv.x, tv.y, tv.z, tv.w};
        unsigned vm = 0;
#pragma unroll
        for (int j = 0; j < 4; j++) if (mm[j] < 1.0f) vm |= 1u << j;  // visible <=> clip(m) < 1
#pragma unroll
        for (int j = 0; j < 4; j++)
            if (vm & (1u << j)) atomicAdd(&sh[f2key(tt[j]) >> 20], 1);

        // assemble 32-bit visibility word across 8 consecutive lanes
        unsigned part = vm << (4 * (lane & 7));
        part |= __shfl_xor_sync(0xFFFFFFFFu, part, 1);
        part |= __shfl_xor_sync(0xFFFFFFFFu, part, 2);
        part |= __shfl_xor_sync(0xFFFFFFFFu, part, 4);
        if ((lane & 7) == 0) vb[idx >> 5] = part;

        // warp-aggregated compaction
        int vc = __popc(vm);
        int sc = vc;
#pragma unroll
        for (int d = 1; d < 32; d <<= 1) {
            int v = __shfl_up_sync(0xFFFFFFFFu, sc, d);
            if (lane >= d) sc += v;
        }
        int wtotal = __shfl_sync(0xFFFFFFFFu, sc, 31);
        int wbase = 0;
        if (lane == 0 && wtotal) wbase = atomicAdd(&blkpos, wtotal);
        wbase = __shfl_sync(0xFFFFFFFFu, wbase, 0);
        int o = wbase + sc - vc;
#pragma unroll
        for (int j = 0; j < 4; j++)
            if (vm & (1u << j)) outv[o++] = tt[j];
    }
    __syncthreads();
    if (threadIdx.x == 0) g_bcnt[s][blockIdx.x] = blkpos;
    for (int i = threadIdx.x; i < 4096; i += 256)
        if (sh[i]) atomicAdd(&g_hist0[s][i], sh[i]);
}

// ---------------- block scan helper ----------------
template <int NB>
__device__ __forceinline__ void scan_find_one(const int* __restrict__ h,
                                              unsigned* pf, int* rem, int shift) {
    constexpr int C = NB / 256;
    const int tid = threadIdx.x, lane = tid & 31, w = tid >> 5;
    __shared__ int wtot[8];
    int c[C]; int tot = 0;
#pragma unroll
    for (int i = 0; i < C; i++) { c[i] = h[tid * C + i]; tot += c[i]; }
    int sc = tot;
#pragma unroll
    for (int d = 1; d < 32; d <<= 1) {
        int v = __shfl_up_sync(0xFFFFFFFFu, sc, d);
        if (lane >= d) sc += v;
    }
    if (lane == 31) wtot[w] = sc;
    const int r = *rem;
    __syncthreads();
    int woff = 0;
#pragma unroll
    for (int i = 0; i < 8; i++) if (i < w) woff += wtot[i];
    int prev = woff + sc - tot;
#pragma unroll
    for (int i = 0; i < C; i++) {
        if (prev <= r && r < prev + c[i]) {
            *pf = ((*pf) << shift) | (unsigned)(tid * C + i);
            *rem = r - prev;
        }
        prev += c[i];
    }
}

// ---------------- K2: ranks + level-0 scan + rep map ----------------
__global__ void k2_setup() {
    const int s = blockIdx.x, tid = threadIdx.x, lane = tid & 31, w = tid >> 5;
    __shared__ int wtot[8];
    int c[16]; int tot = 0;
    const int* h = g_hist0[s];
#pragma unroll
    for (int i = 0; i < 16; i++) { c[i] = h[tid * 16 + i]; tot += c[i]; }
    int sc = tot;
#pragma unroll
    for (int d = 1; d < 32; d <<= 1) {
        int v = __shfl_up_sync(0xFFFFFFFFu, sc, d);
        if (lane >= d) sc += v;
    }
    if (lane == 31) wtot[w] = sc;
    __syncthreads();
    int woff = 0, n = 0;
#pragma unroll
    for (int i = 0; i < 8; i++) { if (i < w) woff += wtot[i]; n += wtot[i]; }
    int prev = woff + sc - tot;

    float nm1 = fmaxf((float)n - 1.0f, 0.0f);
    float p25 = 0.25f * nm1, p75 = 0.75f * nm1;
    float f25 = floorf(p25), f75 = floorf(p75);
    int r[NR];
    r[0] = (n > 0) ? (n - 1) / 2 : 0;
    r[1] = min(max((int)f25, 0), S - 1);
    r[2] = min(max((int)ceilf(p25), 0), S - 1);
    r[3] = min(max((int)f75, 0), S - 1);
    r[4] = min(max((int)ceilf(p75), 0), S - 1);
#pragma unroll
    for (int i = 0; i < 16; i++) {
#pragma unroll
        for (int j = 0; j < NR; j++)
            if (prev <= r[j] && r[j] < prev + c[i]) {
                g_prefix[s * NR + j] = (unsigned)(tid * 16 + i);
                g_rem[s * NR + j]    = r[j] - prev;
            }
        prev += c[i];
    }
    __syncthreads();
    if (tid == 0) {
        g_n[s] = n;
        g_frac[s][0] = p25 - f25;
        g_frac[s][1] = p75 - f75;
        g_mprefix[s] = 0;
        g_mrem[s] = (n > 0) ? (n - 1) / 2 : 0;
        if (n == 0)
            for (int j = 0; j < NR; j++) { g_prefix[s * NR + j] = 0; g_rem[s * NR + j] = 0; }
        for (int j = 0; j < NR; j++) {
            int rep = j;
            for (int j2 = 0; j2 < j; j2++)
                if (g_prefix[s * NR + j2] == g_prefix[s * NR + j]) { rep = j2; break; }
            g_rep[s * NR + j] = rep;
        }
    }
}

// ---------------- K3s: staged gather of target-rank candidates ----------------
// grid (NBLK, B), block 256. Shared staging; shared atomics only on match.
__global__ void __launch_bounds__(256) k3_gather() {
    __shared__ unsigned sbuf[NR][SBUF];
    __shared__ int scnt[NR];
    __shared__ int sbase[NR];
    const int s = blockIdx.y, b = blockIdx.x;
    if (threadIdx.x < NR) scnt[threadIdx.x] = 0;
    __syncthreads();
    const int cnt = g_bcnt[s][b];
    const float* v = g_cmp + (size_t)s * S + (size_t)b * REG;
    const float4* v4 = reinterpret_cast<const float4*>(v);
    unsigned pf[NR]; int dorep[NR];
#pragma unroll
    for (int j = 0; j < NR; j++) {
        dorep[j] = (g_rep[s * NR + j] == j);
        pf[j] = dorep[j] ? g_prefix[s * NR + j] : 0xFFFFFFFFu;  // non-rep never matches
    }
    const int nvec = cnt >> 2;
#pragma unroll 4
    for (int i = threadIdx.x; i < nvec; i += 256) {
        const float4 x = v4[i];
        const float xx[4] = {x.x, x.y, x.z, x.w};
#pragma unroll
        for (int e = 0; e < 4; e++) {
            unsigned key = f2key(xx[e]);
            unsigned top = key >> 20;
#pragma unroll
            for (int j = 0; j < NR; j++) {
                if (top == pf[j]) {
                    int o = atomicAdd(&scnt[j], 1);
                    if (o < SBUF) sbuf[j][o] = key;
                }
            }
        }
    }
    for (int i = (nvec << 2) + threadIdx.x; i < cnt; i += 256) {
        unsigned key = f2key(v[i]);
        unsigned top = key >> 20;
#pragma unroll
        for (int j = 0; j < NR; j++) {
            if (top == pf[j]) {
                int o = atomicAdd(&scnt[j], 1);
                if (o < SBUF) sbuf[j][o] = key;
            }
        }
    }
    __syncthreads();
    if (threadIdx.x < NR) {
        int j = threadIdx.x;
        int c = min(scnt[j], SBUF);
        sbase[j] = c ? atomicAdd(&g_ccnt[s * NR + j], c) : 0;
    }
    __syncthreads();
#pragma unroll
    for (int j = 0; j < NR; j++) {
        int c = min(scnt[j], SBUF);
        for (int i = threadIdx.x; i < c; i += 256) {
            unsigned o = (unsigned)sbase[j] + i;
            if (o < CAPR) g_cand[s][j][o] = sbuf[j][i];
        }
    }
}

// ---------------- K4s: per-rank select from candidates ----------------
__global__ void __launch_bounds__(256) k4_select() {
    const int b = blockIdx.x;          // 0..B*NR-1
    const int s = b / NR, j = b % NR;
    __shared__ int sh[4096];
    __shared__ int wtot[8];
    __shared__ int s_bin, s_rem;
    const int tid = threadIdx.x, lane = tid & 31, w = tid >> 5;
    if (g_n[s] <= 0) { if (tid == 0) g_vals[b] = 0.0f; return; }
    const int rep = g_rep[s * NR + j];
    const unsigned* cand = g_cand[s][rep];
    int cnt = g_ccnt[s * NR + rep]; if (cnt > CAPR) cnt = CAPR;
    const int rem0 = g_rem[b];
    for (int i = tid; i < 4096; i += 256) sh[i] = 0;
    __syncthreads();
    for (int i = tid; i < cnt; i += 256) atomicAdd(&sh[(cand[i] >> 8) & 0xFFF], 1);
    __syncthreads();
    int c[16]; int tot = 0;
#pragma unroll
    for (int i = 0; i < 16; i++) { c[i] = sh[tid * 16 + i]; tot += c[i]; }
    int sc = tot;
#pragma unroll
    for (int d = 1; d < 32; d <<= 1) {
        int v = __shfl_up_sync(0xFFFFFFFFu, sc, d);
        if (lane >= d) sc += v;
    }
    if (lane == 31) wtot[w] = sc;
    __syncthreads();
    int woff = 0;
#pragma unroll
    for (int i = 0; i < 8; i++) if (i < w) woff += wtot[i];
    int prev = woff + sc - tot;
#pragma unroll
    for (int i = 0; i < 16; i++) {
        if (prev <= rem0 && rem0 < prev + c[i]) { s_bin = tid * 16 + i; s_rem = rem0 - prev; }
        prev += c[i];
    }
    __syncthreads();
    const unsigned bin1 = (unsigned)s_bin;
    const int rem1 = s_rem;
    if (tid < 256) sh[tid] = 0;
    __syncthreads();
    for (int i = tid; i < cnt; i += 256) {
        unsigned kk = cand[i];
        if (((kk >> 8) & 0xFFF) == bin1) atomicAdd(&sh[kk & 0xFF], 1);
    }
    __syncthreads();
    if (tid == 0) {
        int r = rem1, cum = 0; unsigned byte = 0;
        for (int x = 0; x < 256; x++) { int cc = sh[x]; if (r < cum + cc) { byte = (unsigned)x; break; } cum += cc; }
        unsigned key = (g_prefix[b] << 20) | (bin1 << 8) | byte;
        g_vals[b] = key2f(key);
    }
}

// ---------------- K6: combine med / q25 / q75 ----------------
__global__ void k6_vals() {
    const int tid = threadIdx.x;  // 1 block, 64 threads
    if (tid < B) {
        const int s = tid;
        g_med[s] = (g_n[s] > 0) ? g_vals[s * NR + 0] : 0.0f;
        g_q25[s] = g_vals[s * NR + 1] + (g_vals[s * NR + 2] - g_vals[s * NR + 1]) * g_frac[s][0];
        g_q75[s] = g_vals[s * NR + 3] + (g_vals[s * NR + 4] - g_vals[s * NR + 3]) * g_frac[s][1];
    }
}

// ---------------- K7: MAD level-0 hist of |t - med| ----------------
__global__ void __launch_bounds__(256) k7_mhist0() {
    __shared__ int sh[2048];
    const int s = blockIdx.y, b = blockIdx.x;
    for (int i = threadIdx.x; i < 2048; i += 256) sh[i] = 0;
    __syncthreads();
    const float med = g_med[s];
    const int cnt = g_bcnt[s][b];
    const float* v = g_cmp + (size_t)s * S + (size_t)b * REG;
    const float4* v4 = reinterpret_cast<const float4*>(v);
    const int nvec = cnt >> 2;
#pragma unroll 4
    for (int i = threadIdx.x; i < nvec; i += 256) {
        const float4 x = v4[i];
        const float xx[4] = {x.x, x.y, x.z, x.w};
#pragma unroll
        for (int e = 0; e < 4; e++)
            atomicAdd(&sh[__float_as_uint(fabsf(xx[e] - med)) >> 20], 1);
    }
    for (int i = (nvec << 2) + threadIdx.x; i < cnt; i += 256)
        atomicAdd(&sh[__float_as_uint(fabsf(v[i] - med)) >> 20], 1);
    __syncthreads();
    for (int i = threadIdx.x; i < 2048; i += 256)
        if (sh[i]) atomicAdd(&g_mhist0[s][i], sh[i]);
}

// ---------------- K8: MAD level-0 scan ----------------
__global__ void k8_mscan0() {
    const int s = blockIdx.x;
    if (g_n[s] <= 0) return;
    scan_find_one<2048>(g_mhist0[s], &g_mprefix[s], &g_mrem[s], 0);
}

// ---------------- K9s: staged gather of MAD candidates ----------------
__global__ void __launch_bounds__(256) k9_gather() {
    __shared__ unsigned sbuf[SBUFM];
    __shared__ int scnt, sbase;
    const int s = blockIdx.y, b = blockIdx.x;
    if (threadIdx.x == 0) scnt = 0;
    __syncthreads();
    const float med = g_med[s];
    const unsigned pf = g_mprefix[s];
    const int cnt = g_bcnt[s][b];
    const float* v = g_cmp + (size_t)s * S + (size_t)b * REG;
    const float4* v4 = reinterpret_cast<const float4*>(v);
    const int nvec = cnt >> 2;
#pragma unroll 4
    for (int i = threadIdx.x; i < nvec; i += 256) {
        const float4 x = v4[i];
        const float xx[4] = {x.x, x.y, x.z, x.w};
#pragma unroll
        for (int e = 0; e < 4; e++) {
            unsigned u = __float_as_uint(fabsf(xx[e] - med));
            if ((u >> 20) == pf) {
                int o = atomicAdd(&scnt, 1);
                if (o < SBUFM) sbuf[o] = u;
            }
        }
    }
    for (int i = (nvec << 2) + threadIdx.x; i < cnt; i += 256) {
        unsigned u = __float_as_uint(fabsf(v[i] - med));
        if ((u >> 20) == pf) {
            int o = atomicAdd(&scnt, 1);
            if (o < SBUFM) sbuf[o] = u;
        }
    }
    __syncthreads();
    if (threadIdx.x == 0) {
        int c = min(scnt, SBUFM);
        sbase = c ? atomicAdd(&g_mccnt[s], c) : 0;
    }
    __syncthreads();
    {
        int c = min(scnt, SBUFM);
        for (int i = threadIdx.x; i < c; i += 256) {
            unsigned o = (unsigned)sbase + i;
            if (o < CAPM) g_mcand[s][o] = sbuf[i];
        }
    }
}

// ---------------- K10s: select MAD from candidates ----------------
__global__ void __launch_bounds__(256) k10_select() {
    const int s = blockIdx.x;
    __shared__ int sh[4096];
    __shared__ int wtot[8];
    __shared__ int s_bin, s_rem;
    const int tid = threadIdx.x, lane = tid & 31, w = tid >> 5;
    if (g_n[s] <= 0) { if (tid == 0) g_madv[s] = 0.0f; return; }
    const unsigned* cand = g_mcand[s];
    int cnt = g_mccnt[s]; if (cnt > CAPM) cnt = CAPM;
    const int rem0 = g_mrem[s];
    for (int i = tid; i < 4096; i += 256) sh[i] = 0;
    __syncthreads();
    for (int i = tid; i < cnt; i += 256) atomicAdd(&sh[(cand[i] >> 8) & 0xFFF], 1);
    __syncthreads();
    int c[16]; int tot = 0;
#pragma unroll
    for (int i = 0; i < 16; i++) { c[i] = sh[tid * 16 + i]; tot += c[i]; }
    int sc = tot;
#pragma unroll
    for (int d = 1; d < 32; d <<= 1) {
        int v = __shfl_up_sync(0xFFFFFFFFu, sc, d);
        if (lane >= d) sc += v;
    }
    if (lane == 31) wtot[w] = sc;
    __syncthreads();
    int woff = 0;
#pragma unroll
    for (int i = 0; i < 8; i++) if (i < w) woff += wtot[i];
    int prev = woff + sc - tot;
#pragma unroll
    for (int i = 0; i < 16; i++) {
        if (prev <= rem0 && rem0 < prev + c[i]) { s_bin = tid * 16 + i; s_rem = rem0 - prev; }
        prev += c[i];
    }
    __syncthreads();
    const unsigned bin1 = (unsigned)s_bin;
    const int rem1 = s_rem;
    if (tid < 256) sh[tid] = 0;
    __syncthreads();
    for (int i = tid; i < cnt; i += 256) {
        unsigned kk = cand[i];
        if (((kk >> 8) & 0xFFF) == bin1) atomicAdd(&sh[kk & 0xFF], 1);
    }
    __syncthreads();
    if (tid == 0) {
        int r = rem1, cum = 0; unsigned byte = 0;
        for (int x = 0; x < 256; x++) { int cc = sh[x]; if (r < cum + cc) { byte = (unsigned)x; break; } cum += cc; }
        g_madv[s] = __uint_as_float((g_mprefix[s] << 20) | (bin1 << 8) | byte);
    }
}

// ---------------- K12: final per-sample scalars + num_masked ----------------
__global__ void k12_final() {
    const int tid = threadIdx.x;  // 32 threads
    if (tid < B) {
        const int s = tid, n = g_n[s];
        float mad = (n > 0) ? g_madv[s] : 0.0f;
        float scaled = 1.4826f * mad;
        float iqr = fmaxf((g_q75[s] - g_q25[s]) / 1.35f, 1e-6f);
        float fm = (scaled < 0.1f) ? iqr : scaled;
        if (n <= 0) fm = 1.0f;
        int dn = (n > 0) && (fm > 0.1f);
        g_scale[s] = dn ? (1.0f / fm) : 1.0f;   // (p-med)/fm - (t-med)/fm == (p-t)/fm
    }
    if (tid == 0) {
        double nm = (double)B * (double)S;      // binary mask: sum(mask) = total - visible
        for (int s2 = 0; s2 < B; s2++) nm -= (double)g_n[s2];
        g_nmask = nm;
    }
}

// ---------------- K13: masked-MSE using visbits (no mask read) ----------------
__global__ void __launch_bounds__(256) k13_loss(const float* __restrict__ pred,
                                                const float* __restrict__ tgt) {
    const int s = blockIdx.y;
    const float sc = g_scale[s];
    const size_t off = (size_t)s * S;
    const float* p = pred + off;
    const float* t = tgt + off;
    const unsigned* vb = g_visbits + s * WPS;
    const int base = blockIdx.x * 8192;
    float ls = 0.0f;
#pragma unroll
    for (int k = 0; k < 8; k++) {
        const int idx = base + k * 1024 + threadIdx.x * 4;
        const float4 pv = *reinterpret_cast<const float4*>(p + idx);
        const float4 tv = *reinterpret_cast<const float4*>(t + idx);
        const unsigned nib = (vb[idx >> 5] >> (idx & 31)) & 0xF;
        const float pp[4] = {pv.x, pv.y, pv.z, pv.w};
        const float tt[4] = {tv.x, tv.y, tv.z, tv.w};
#pragma unroll
        for (int j = 0; j < 4; j++) {
            float d = (pp[j] - tt[j]) * sc;
            float l = fminf(d * d, 100.0f);
            ls += ((nib >> j) & 1u) ? 0.0f : l;   // masked <=> not visible
        }
    }
    for (int o = 16; o; o >>= 1) ls += __shfl_down_sync(0xFFFFFFFFu, ls, o);
    __shared__ float wls[8];
    if ((threadIdx.x & 31) == 0) wls[threadIdx.x >> 5] = ls;
    __syncthreads();
    if (threadIdx.x == 0) {
        double a = 0.0;
        for (int i = 0; i < 8; i++) a += (double)wls[i];
        atomicAdd(&g_lsum, a);
    }
}

// ---------------- K14: write scalar output ----------------
__global__ void k14_out(float* out) {
    double nm = g_nmask;
    out[0] = (nm > 0.0) ? (float)(g_lsum / fmax(nm, 1.0)) : 0.0f;
}

// ---------------- launch ----------------
extern "C" void kernel_launch(void* const* d_in, const int* in_sizes, int n_in,
                              void* d_out, int out_size) {
    const float* pred = (const float*)d_in[0];
    const float* tgt  = (const float*)d_in[1];
    const float* msk  = (const float*)d_in[2];
    float* out = (float*)d_out;

    dim3 greg(NBLK, B), gloss(512, B);

    k0_zero<<<64, 256>>>();
    k1_compact<<<greg, 256>>>(tgt, msk);
    k2_setup<<<B, 256>>>();
    k3_gather<<<greg, 256>>>();
    k4_select<<<B * NR, 256>>>();
    k6_vals<<<1, 64>>>();
    k7_mhist0<<<greg, 256>>>();
    k8_mscan0<<<B, 256>>>();
    k9_gather<<<greg, 256>>>();
    k10_select<<<B, 256>>>();
    k12_final<<<1, 32>>>();
    k13_loss<<<gloss, 256>>>(pred, tgt);
    k14_out<<<1, 1>>>(out);
}

// round 10
// speedup vs baseline: 2.7754x; 1.1627x over previous
#include <cuda_runtime.h>
#include <stdint.h>
#include <math.h>

#define B 8
#define S 4194304              // elements per sample (64*256*256)
#define NR 5                   // ranks: med, q25lo, q25hi, q75lo, q75hi
#define NBLK 128               // K1 blocks per sample == compact regions
#define REG 32768              // elements per region (S/NBLK)
#define CAPR 262144            // candidate capacity per target rank
#define CAPM 524288            // candidate capacity for MAD rank
#define SBUF 1536              // per-block staging per rank
#define SBUFM 4096             // per-block staging for MAD

// ---------------- device scratch (static; no allocations) ----------------
static __device__ float    g_cmp[(size_t)B * S];   // compacted visible values
static __device__ int      g_bcnt[B][NBLK];
static __device__ int      g_n[B];
static __device__ int      g_hist0[B][4096];
static __device__ int      g_mhist0[B][2048];
static __device__ unsigned g_cand[B][NR][CAPR];
static __device__ unsigned g_mcand[B][CAPM];
static __device__ int      g_ccnt[B * NR];
static __device__ int      g_mccnt[B];
static __device__ unsigned g_prefix[B * NR];
static __device__ int      g_rem[B * NR];
static __device__ int      g_rep[B * NR];
static __device__ float    g_frac[B][2];
static __device__ float    g_vals[B * NR];         // [0]=med per sample
static __device__ unsigned g_mprefix[B];
static __device__ int      g_mrem[B];
static __device__ float    g_madv[B];
static __device__ float    g_scale[B];
static __device__ double   g_s2[B];                // sum of (p-t)^2 over masked elems
static __device__ unsigned g_m2[B];                // max (p-t)^2 bits (non-neg float)
static __device__ int      g_flag;                 // 1 -> need exact fallback
static __device__ double   g_factored;             // factored loss numerator
static __device__ double   g_lsum;                 // fallback loss numerator
static __device__ double   g_nmask;

__device__ __forceinline__ unsigned f2key(float x) {
    unsigned u = __float_as_uint(x);
    return (u & 0x80000000u) ? ~u : (u | 0x80000000u);
}
__device__ __forceinline__ float key2f(unsigned k) {
    unsigned u = (k & 0x80000000u) ? (k & 0x7FFFFFFFu) : ~k;
    return __uint_as_float(u);
}

// ---------------- K0: zero scratch ----------------
__global__ void k0_zero() {
    int tid = blockIdx.x * blockDim.x + threadIdx.x;
    int st = gridDim.x * blockDim.x;
    int* p;
    p = (int*)g_hist0;  for (int i = tid; i < B * 4096; i += st) p[i] = 0;
    p = (int*)g_mhist0; for (int i = tid; i < B * 2048; i += st) p[i] = 0;
    if (tid < B * NR) g_ccnt[tid] = 0;
    if (tid < B) { g_mccnt[tid] = 0; g_s2[tid] = 0.0; g_m2[tid] = 0u; }
    if (tid == 0) { g_lsum = 0.0; g_flag = 0; }
}

// ---------------- K1: fused compact + hist + masked-SSE ----------------
// grid (NBLK, B), block 256. Reads pred+tgt+mask once (402 MB total).
__global__ void __launch_bounds__(256) k1_fused(const float* __restrict__ pred,
                                                const float* __restrict__ tgt,
                                                const float* __restrict__ msk) {
    __shared__ int sh[4096];
    __shared__ int blkpos;
    __shared__ float wmax[8];
    __shared__ float wsum[8];
    const int s = blockIdx.y;
    for (int i = threadIdx.x; i < 4096; i += 256) sh[i] = 0;
    if (threadIdx.x == 0) blkpos = 0;
    __syncthreads();

    const size_t soff = (size_t)s * S;
    const float* pr = pred + soff;
    const float* t  = tgt + soff;
    const float* m  = msk + soff;
    float* outv = g_cmp + soff + (size_t)blockIdx.x * REG;
    const int base = blockIdx.x * REG;
    const int lane = threadIdx.x & 31;

    float ls = 0.0f, lm = 0.0f;
    for (int k = 0; k < 32; k++) {
        const int idx = base + k * 1024 + threadIdx.x * 4;
        const float4 mv = *reinterpret_cast<const float4*>(m + idx);
        const float4 tv = *reinterpret_cast<const float4*>(t + idx);
        const float4 pv = *reinterpret_cast<const float4*>(pr + idx);
        const float mm[4] = {mv.x, mv.y, mv.z, mv.w};
        const float tt[4] = {tv.x, tv.y, tv.z, tv.w};
        const float pp[4] = {pv.x, pv.y, pv.z, pv.w};
        unsigned vm = 0;
#pragma unroll
        for (int j = 0; j < 4; j++) {
            if (mm[j] < 1.0f) {                       // visible <=> clip(m) < 1
                vm |= 1u << j;
                atomicAdd(&sh[f2key(tt[j]) >> 20], 1);
            } else {                                  // masked: accumulate (p-t)^2
                float d = pp[j] - tt[j];
                float l = d * d;
                ls += l;
                lm = fmaxf(lm, l);
            }
        }
        // warp-aggregated compaction of visible values
        int vc = __popc(vm);
        int sc = vc;
#pragma unroll
        for (int d = 1; d < 32; d <<= 1) {
            int v = __shfl_up_sync(0xFFFFFFFFu, sc, d);
            if (lane >= d) sc += v;
        }
        int wtotal = __shfl_sync(0xFFFFFFFFu, sc, 31);
        int wbase = 0;
        if (lane == 0 && wtotal) wbase = atomicAdd(&blkpos, wtotal);
        wbase = __shfl_sync(0xFFFFFFFFu, wbase, 0);
        int o = wbase + sc - vc;
#pragma unroll
        for (int j = 0; j < 4; j++)
            if (vm & (1u << j)) outv[o++] = tt[j];
    }
    // block reduce ls (sum) and lm (max)
    for (int o = 16; o; o >>= 1) {
        ls += __shfl_down_sync(0xFFFFFFFFu, ls, o);
        lm = fmaxf(lm, __shfl_down_sync(0xFFFFFFFFu, lm, o));
    }
    const int w = threadIdx.x >> 5;
    if (lane == 0) { wsum[w] = ls; wmax[w] = lm; }
    __syncthreads();
    if (threadIdx.x == 0) {
        g_bcnt[s][blockIdx.x] = blkpos;
        double a = 0.0; float mx = 0.0f;
        for (int i = 0; i < 8; i++) { a += (double)wsum[i]; mx = fmaxf(mx, wmax[i]); }
        atomicAdd(&g_s2[s], a);
        atomicMax(&g_m2[s], __float_as_uint(mx));
    }
    __syncthreads();
    for (int i = threadIdx.x; i < 4096; i += 256)
        if (sh[i]) atomicAdd(&g_hist0[s][i], sh[i]);
}

// ---------------- block scan helper ----------------
template <int NB>
__device__ __forceinline__ void scan_find_one(const int* __restrict__ h,
                                              unsigned* pf, int* rem, int shift) {
    constexpr int C = NB / 256;
    const int tid = threadIdx.x, lane = tid & 31, w = tid >> 5;
    __shared__ int wtot[8];
    int c[C]; int tot = 0;
#pragma unroll
    for (int i = 0; i < C; i++) { c[i] = h[tid * C + i]; tot += c[i]; }
    int sc = tot;
#pragma unroll
    for (int d = 1; d < 32; d <<= 1) {
        int v = __shfl_up_sync(0xFFFFFFFFu, sc, d);
        if (lane >= d) sc += v;
    }
    if (lane == 31) wtot[w] = sc;
    const int r = *rem;
    __syncthreads();
    int woff = 0;
#pragma unroll
    for (int i = 0; i < 8; i++) if (i < w) woff += wtot[i];
    int prev = woff + sc - tot;
#pragma unroll
    for (int i = 0; i < C; i++) {
        if (prev <= r && r < prev + c[i]) {
            *pf = ((*pf) << shift) | (unsigned)(tid * C + i);
            *rem = r - prev;
        }
        prev += c[i];
    }
}

// ---------------- K2: ranks + level-0 scan + rep map ----------------
__global__ void k2_setup() {
    const int s = blockIdx.x, tid = threadIdx.x, lane = tid & 31, w = tid >> 5;
    __shared__ int wtot[8];
    int c[16]; int tot = 0;
    const int* h = g_hist0[s];
#pragma unroll
    for (int i = 0; i < 16; i++) { c[i] = h[tid * 16 + i]; tot += c[i]; }
    int sc = tot;
#pragma unroll
    for (int d = 1; d < 32; d <<= 1) {
        int v = __shfl_up_sync(0xFFFFFFFFu, sc, d);
        if (lane >= d) sc += v;
    }
    if (lane == 31) wtot[w] = sc;
    __syncthreads();
    int woff = 0, n = 0;
#pragma unroll
    for (int i = 0; i < 8; i++) { if (i < w) woff += wtot[i]; n += wtot[i]; }
    int prev = woff + sc - tot;

    float nm1 = fmaxf((float)n - 1.0f, 0.0f);
    float p25 = 0.25f * nm1, p75 = 0.75f * nm1;
    float f25 = floorf(p25), f75 = floorf(p75);
    int r[NR];
    r[0] = (n > 0) ? (n - 1) / 2 : 0;
    r[1] = min(max((int)f25, 0), S - 1);
    r[2] = min(max((int)ceilf(p25), 0), S - 1);
    r[3] = min(max((int)f75, 0), S - 1);
    r[4] = min(max((int)ceilf(p75), 0), S - 1);
#pragma unroll
    for (int i = 0; i < 16; i++) {
#pragma unroll
        for (int j = 0; j < NR; j++)
            if (prev <= r[j] && r[j] < prev + c[i]) {
                g_prefix[s * NR + j] = (unsigned)(tid * 16 + i);
                g_rem[s * NR + j]    = r[j] - prev;
            }
        prev += c[i];
    }
    __syncthreads();
    if (tid == 0) {
        g_n[s] = n;
        g_frac[s][0] = p25 - f25;
        g_frac[s][1] = p75 - f75;
        g_mprefix[s] = 0;
        g_mrem[s] = (n > 0) ? (n - 1) / 2 : 0;
        if (n == 0)
            for (int j = 0; j < NR; j++) { g_prefix[s * NR + j] = 0; g_rem[s * NR + j] = 0; }
        for (int j = 0; j < NR; j++) {
            int rep = j;
            for (int j2 = 0; j2 < j; j2++)
                if (g_prefix[s * NR + j2] == g_prefix[s * NR + j]) { rep = j2; break; }
            g_rep[s * NR + j] = rep;
        }
    }
}

// ---------------- K3s: staged gather of target-rank candidates ----------------
__global__ void __launch_bounds__(256) k3_gather() {
    __shared__ unsigned sbuf[NR][SBUF];
    __shared__ int scnt[NR];
    __shared__ int sbase[NR];
    const int s = blockIdx.y, b = blockIdx.x;
    if (threadIdx.x < NR) scnt[threadIdx.x] = 0;
    __syncthreads();
    const int cnt = g_bcnt[s][b];
    const float* v = g_cmp + (size_t)s * S + (size_t)b * REG;
    const float4* v4 = reinterpret_cast<const float4*>(v);
    unsigned pf[NR]; int dorep[NR];
#pragma unroll
    for (int j = 0; j < NR; j++) {
        dorep[j] = (g_rep[s * NR + j] == j);
        pf[j] = dorep[j] ? g_prefix[s * NR + j] : 0xFFFFFFFFu;
    }
    const int nvec = cnt >> 2;
#pragma unroll 4
    for (int i = threadIdx.x; i < nvec; i += 256) {
        const float4 x = v4[i];
        const float xx[4] = {x.x, x.y, x.z, x.w};
#pragma unroll
        for (int e = 0; e < 4; e++) {
            unsigned key = f2key(xx[e]);
            unsigned top = key >> 20;
#pragma unroll
            for (int j = 0; j < NR; j++) {
                if (top == pf[j]) {
                    int o = atomicAdd(&scnt[j], 1);
                    if (o < SBUF) sbuf[j][o] = key;
                }
            }
        }
    }
    for (int i = (nvec << 2) + threadIdx.x; i < cnt; i += 256) {
        unsigned key = f2key(v[i]);
        unsigned top = key >> 20;
#pragma unroll
        for (int j = 0; j < NR; j++) {
            if (top == pf[j]) {
                int o = atomicAdd(&scnt[j], 1);
                if (o < SBUF) sbuf[j][o] = key;
            }
        }
    }
    __syncthreads();
    if (threadIdx.x < NR) {
        int j = threadIdx.x;
        int c = min(scnt[j], SBUF);
        sbase[j] = c ? atomicAdd(&g_ccnt[s * NR + j], c) : 0;
    }
    __syncthreads();
#pragma unroll
    for (int j = 0; j < NR; j++) {
        int c = min(scnt[j], SBUF);
        for (int i = threadIdx.x; i < c; i += 256) {
            unsigned o = (unsigned)sbase[j] + i;
            if (o < CAPR) g_cand[s][j][o] = sbuf[j][i];
        }
    }
}

// ---------------- K4s: per-rank select from candidates ----------------
__global__ void __launch_bounds__(256) k4_select() {
    const int b = blockIdx.x;          // 0..B*NR-1
    const int s = b / NR, j = b % NR;
    __shared__ int sh[4096];
    __shared__ int wtot[8];
    __shared__ int s_bin, s_rem;
    const int tid = threadIdx.x, lane = tid & 31, w = tid >> 5;
    if (g_n[s] <= 0) { if (tid == 0) g_vals[b] = 0.0f; return; }
    const int rep = g_rep[s * NR + j];
    const unsigned* cand = g_cand[s][rep];
    int cnt = g_ccnt[s * NR + rep]; if (cnt > CAPR) cnt = CAPR;
    const int rem0 = g_rem[b];
    for (int i = tid; i < 4096; i += 256) sh[i] = 0;
    __syncthreads();
    for (int i = tid; i < cnt; i += 256) atomicAdd(&sh[(cand[i] >> 8) & 0xFFF], 1);
    __syncthreads();
    int c[16]; int tot = 0;
#pragma unroll
    for (int i = 0; i < 16; i++) { c[i] = sh[tid * 16 + i]; tot += c[i]; }
    int sc = tot;
#pragma unroll
    for (int d = 1; d < 32; d <<= 1) {
        int v = __shfl_up_sync(0xFFFFFFFFu, sc, d);
        if (lane >= d) sc += v;
    }
    if (lane == 31) wtot[w] = sc;
    __syncthreads();
    int woff = 0;
#pragma unroll
    for (int i = 0; i < 8; i++) if (i < w) woff += wtot[i];
    int prev = woff + sc - tot;
#pragma unroll
    for (int i = 0; i < 16; i++) {
        if (prev <= rem0 && rem0 < prev + c[i]) { s_bin = tid * 16 + i; s_rem = rem0 - prev; }
        prev += c[i];
    }
    __syncthreads();
    const unsigned bin1 = (unsigned)s_bin;
    const int rem1 = s_rem;
    if (tid < 256) sh[tid] = 0;
    __syncthreads();
    for (int i = tid; i < cnt; i += 256) {
        unsigned kk = cand[i];
        if (((kk >> 8) & 0xFFF) == bin1) atomicAdd(&sh[kk & 0xFF], 1);
    }
    __syncthreads();
    if (tid == 0) {
        int r = rem1, cum = 0; unsigned byte = 0;
        for (int x = 0; x < 256; x++) { int cc = sh[x]; if (r < cum + cc) { byte = (unsigned)x; break; } cum += cc; }
        unsigned key = (g_prefix[b] << 20) | (bin1 << 8) | byte;
        g_vals[b] = key2f(key);
    }
}

// ---------------- K7: MAD level-0 hist of |t - med| ----------------
__global__ void __launch_bounds__(256) k7_mhist0() {
    __shared__ int sh[2048];
    const int s = blockIdx.y, b = blockIdx.x;
    for (int i = threadIdx.x; i < 2048; i += 256) sh[i] = 0;
    __syncthreads();
    const float med = g_vals[s * NR];   // med (0 when n==0)
    const int cnt = g_bcnt[s][b];
    const float* v = g_cmp + (size_t)s * S + (size_t)b * REG;
    const float4* v4 = reinterpret_cast<const float4*>(v);
    const int nvec = cnt >> 2;
#pragma unroll 4
    for (int i = threadIdx.x; i < nvec; i += 256) {
        const float4 x = v4[i];
        const float xx[4] = {x.x, x.y, x.z, x.w};
#pragma unroll
        for (int e = 0; e < 4; e++)
            atomicAdd(&sh[__float_as_uint(fabsf(xx[e] - med)) >> 20], 1);
    }
    for (int i = (nvec << 2) + threadIdx.x; i < cnt; i += 256)
        atomicAdd(&sh[__float_as_uint(fabsf(v[i] - med)) >> 20], 1);
    __syncthreads();
    for (int i = threadIdx.x; i < 2048; i += 256)
        if (sh[i]) atomicAdd(&g_mhist0[s][i], sh[i]);
}

// ---------------- K8: MAD level-0 scan ----------------
__global__ void k8_mscan0() {
    const int s = blockIdx.x;
    if (g_n[s] <= 0) return;
    scan_find_one<2048>(g_mhist0[s], &g_mprefix[s], &g_mrem[s], 0);
}

// ---------------- K9s: staged gather of MAD candidates ----------------
__global__ void __launch_bounds__(256) k9_gather() {
    __shared__ unsigned sbuf[SBUFM];
    __shared__ int scnt, sbase;
    const int s = blockIdx.y, b = blockIdx.x;
    if (threadIdx.x == 0) scnt = 0;
    __syncthreads();
    const float med = g_vals[s * NR];
    const unsigned pf = g_mprefix[s];
    const int cnt = g_bcnt[s][b];
    const float* v = g_cmp + (size_t)s * S + (size_t)b * REG;
    const float4* v4 = reinterpret_cast<const float4*>(v);
    const int nvec = cnt >> 2;
#pragma unroll 4
    for (int i = threadIdx.x; i < nvec; i += 256) {
        const float4 x = v4[i];
        const float xx[4] = {x.x, x.y, x.z, x.w};
#pragma unroll
        for (int e = 0; e < 4; e++) {
            unsigned u = __float_as_uint(fabsf(xx[e] - med));
            if ((u >> 20) == pf) {
                int o = atomicAdd(&scnt, 1);
                if (o < SBUFM) sbuf[o] = u;
            }
        }
    }
    for (int i = (nvec << 2) + threadIdx.x; i < cnt; i += 256) {
        unsigned u = __float_as_uint(fabsf(v[i] - med));
        if ((u >> 20) == pf) {
            int o = atomicAdd(&scnt, 1);
            if (o < SBUFM) sbuf[o] = u;
        }
    }
    __syncthreads();
    if (threadIdx.x == 0) {
        int c = min(scnt, SBUFM);
        sbase = c ? atomicAdd(&g_mccnt[s], c) : 0;
    }
    __syncthreads();
    {
        int c = min(scnt, SBUFM);
        for (int i = threadIdx.x; i < c; i += 256) {
            unsigned o = (unsigned)sbase + i;
            if (o < CAPM) g_mcand[s][o] = sbuf[i];
        }
    }
}

// ---------------- K10s: select MAD from candidates ----------------
__global__ void __launch_bounds__(256) k10_select() {
    const int s = blockIdx.x;
    __shared__ int sh[4096];
    __shared__ int wtot[8];
    __shared__ int s_bin, s_rem;
    const int tid = threadIdx.x, lane = tid & 31, w = tid >> 5;
    if (g_n[s] <= 0) { if (tid == 0) g_madv[s] = 0.0f; return; }
    const unsigned* cand = g_mcand[s];
    int cnt = g_mccnt[s]; if (cnt > CAPM) cnt = CAPM;
    const int rem0 = g_mrem[s];
    for (int i = tid; i < 4096; i += 256) sh[i] = 0;
    __syncthreads();
    for (int i = tid; i < cnt; i += 256) atomicAdd(&sh[(cand[i] >> 8) & 0xFFF], 1);
    __syncthreads();
    int c[16]; int tot = 0;
#pragma unroll
    for (int i = 0; i < 16; i++) { c[i] = sh[tid * 16 + i]; tot += c[i]; }
    int sc = tot;
#pragma unroll
    for (int d = 1; d < 32; d <<= 1) {
        int v = __shfl_up_sync(0xFFFFFFFFu, sc, d);
        if (lane >= d) sc += v;
    }
    if (lane == 31) wtot[w] = sc;
    __syncthreads();
    int woff = 0;
#pragma unroll
    for (int i = 0; i < 8; i++) if (i < w) woff += wtot[i];
    int prev = woff + sc - tot;
#pragma unroll
    for (int i = 0; i < 16; i++) {
        if (prev <= rem0 && rem0 < prev + c[i]) { s_bin = tid * 16 + i; s_rem = rem0 - prev; }
        prev += c[i];
    }
    __syncthreads();
    const unsigned bin1 = (unsigned)s_bin;
    const int rem1 = s_rem;
    if (tid < 256) sh[tid] = 0;
    __syncthreads();
    for (int i = tid; i < cnt; i += 256) {
        unsigned kk = cand[i];
        if (((kk >> 8) & 0xFFF) == bin1) atomicAdd(&sh[kk & 0xFF], 1);
    }
    __syncthreads();
    if (tid == 0) {
        int r = rem1, cum = 0; unsigned byte = 0;
        for (int x = 0; x < 256; x++) { int cc = sh[x]; if (r < cum + cc) { byte = (unsigned)x; break; } cum += cc; }
        g_madv[s] = __uint_as_float((g_mprefix[s] << 20) | (bin1 << 8) | byte);
    }
}

// ---------------- K12: scalars + factored loss + clamp guard ----------------
__global__ void k12_final() {
    const int tid = threadIdx.x;  // 32 threads
    if (tid < B) {
        const int s = tid, n = g_n[s];
        float q25 = g_vals[s * NR + 1] + (g_vals[s * NR + 2] - g_vals[s * NR + 1]) * g_frac[s][0];
        float q75 = g_vals[s * NR + 3] + (g_vals[s * NR + 4] - g_vals[s * NR + 3]) * g_frac[s][1];
        float mad = (n > 0) ? g_madv[s] : 0.0f;
        float scaled = 1.4826f * mad;
        float iqr = fmaxf((q75 - q25) / 1.35f, 1e-6f);
        float fm = (scaled < 0.1f) ? iqr : scaled;
        if (n <= 0) fm = 1.0f;
        int dn = (n > 0) && (fm > 0.1f);
        float sc = dn ? (1.0f / fm) : 1.0f;
        g_scale[s] = sc;
        // clamp guard: fallback unless max (p-t)^2 * sc^2 provably <= 100 (NaN-safe)
        float m2 = __uint_as_float(g_m2[s]);
        if (!(m2 * sc * sc <= 100.0f)) atomicExch(&g_flag, 1);
    }
    __syncthreads();
    if (tid == 0) {
        double nm = (double)B * (double)S;
        double fl = 0.0;
        for (int s2 = 0; s2 < B; s2++) {
            nm -= (double)g_n[s2];
            double sc = (double)g_scale[s2];
            fl += sc * sc * g_s2[s2];
        }
        g_nmask = nm;
        g_factored = fl;
    }
}

// ---------------- K13fb: exact fallback (early-exit when clamp never binds) ----------------
__global__ void __launch_bounds__(256) k13_fallback(const float* __restrict__ pred,
                                                    const float* __restrict__ tgt,
                                                    const float* __restrict__ msk) {
    if (g_flag == 0) return;
    const int s = blockIdx.y;
    const float sc = g_scale[s];
    const size_t off = (size_t)s * S;
    const float* p = pred + off;
    const float* t = tgt + off;
    const float* m = msk + off;
    const int base = blockIdx.x * 8192;
    float ls = 0.0f;
#pragma unroll
    for (int k = 0; k < 8; k++) {
        const int idx = base + k * 1024 + threadIdx.x * 4;
        const float4 pv = *reinterpret_cast<const float4*>(p + idx);
        const float4 tv = *reinterpret_cast<const float4*>(t + idx);
        const float4 mv = *reinterpret_cast<const float4*>(m + idx);
        const float pp[4] = {pv.x, pv.y, pv.z, pv.w};
        const float tt[4] = {tv.x, tv.y, tv.z, tv.w};
        const float mm[4] = {mv.x, mv.y, mv.z, mv.w};
#pragma unroll
        for (int j = 0; j < 4; j++) {
            float mc = fminf(fmaxf(mm[j], 0.0f), 1.0f);
            float d = (pp[j] - tt[j]) * sc;
            float l = d * d;
            if (isnan(l) || isinf(l)) l = 100.0f;
            l = fminf(fmaxf(l, 0.0f), 100.0f);
            ls += l * mc;
        }
    }
    for (int o = 16; o; o >>= 1) ls += __shfl_down_sync(0xFFFFFFFFu, ls, o);
    __shared__ float wls[8];
    if ((threadIdx.x & 31) == 0) wls[threadIdx.x >> 5] = ls;
    __syncthreads();
    if (threadIdx.x == 0) {
        double a = 0.0;
        for (int i = 0; i < 8; i++) a += (double)wls[i];
        atomicAdd(&g_lsum, a);
    }
}

// ---------------- K14: write scalar output ----------------
__global__ void k14_out(float* out) {
    double nm = g_nmask;
    double num = g_flag ? g_lsum : g_factored;
    out[0] = (nm > 0.0) ? (float)(num / fmax(nm, 1.0)) : 0.0f;
}

// ---------------- launch ----------------
extern "C" void kernel_launch(void* const* d_in, const int* in_sizes, int n_in,
                              void* d_out, int out_size) {
    const float* pred = (const float*)d_in[0];
    const float* tgt  = (const float*)d_in[1];
    const float* msk  = (const float*)d_in[2];
    float* out = (float*)d_out;

    dim3 greg(NBLK, B), gloss(512, B);

    k0_zero<<<64, 256>>>();
    k1_fused<<<greg, 256>>>(pred, tgt, msk);
    k2_setup<<<B, 256>>>();
    k3_gather<<<greg, 256>>>();
    k4_select<<<B * NR, 256>>>();
    k7_mhist0<<<greg, 256>>>();
    k8_mscan0<<<B, 256>>>();
    k9_gather<<<greg, 256>>>();
    k10_select<<<B, 256>>>();
    k12_final<<<1, 32>>>();
    k13_fallback<<<gloss, 256>>>(pred, tgt, msk);
    k14_out<<<1, 1>>>(out);
}